// round 13
// baseline (speedup 1.0000x reference)
#include <cuda_runtime.h>
#include <cuda_fp16.h>
#include <math.h>

#define MAXN 100000
#define MAXE 1600000

// ---------------- scratch ----------------
__device__ int     g_indeg[MAXN];
__device__ int     g_rowstart[MAXN];
__device__ int     g_cursor[MAXN];
__device__ int     g_bsum[256];
__device__ float   g_dis[MAXN];
__device__ int     g_csr[MAXE];
__device__ __half2 g_h0h[(size_t)MAXN * 32];    // fp16 dis-prescaled x@W1
__device__ float   g_h [(size_t)MAXN * 64];     // fp32 normalized hidden
__device__ __half2 g_ggh[(size_t)MAXN * 32];    // fp16 dis-prescaled (mu,ls) interleaved
__device__ __half  g_zh [(size_t)MAXN * 32];    // fp16 z

// ---------------- graph preprocessing ----------------
__global__ void init_kernel(int n) {
    int i = blockIdx.x * blockDim.x + threadIdx.x;
    if (i < n) g_indeg[i] = 0;
}

__global__ void hist_kernel(const int* __restrict__ dst, int E) {
    int e = blockIdx.x * blockDim.x + threadIdx.x;
    if (e < E) atomicAdd(&g_indeg[dst[e]], 1);
}

__global__ void dis_kernel(int n) {
    int i = blockIdx.x * blockDim.x + threadIdx.x;
    if (i < n) g_dis[i] = rsqrtf((float)(g_indeg[i] + 1));
}

__global__ void scan1_kernel(int n) {
    __shared__ int sm[1024];
    int t = threadIdx.x;
    int i = blockIdx.x * 1024 + t;
    int v = (i < n) ? g_indeg[i] : 0;
    sm[t] = v;
    __syncthreads();
#pragma unroll
    for (int o = 1; o < 1024; o <<= 1) {
        int tv = (t >= o) ? sm[t - o] : 0;
        __syncthreads();
        sm[t] += tv;
        __syncthreads();
    }
    if (i < n) g_rowstart[i] = sm[t] - v;
    if (t == 1023) g_bsum[blockIdx.x] = sm[1023];
}

__global__ void scan2_kernel(int nb) {
    __shared__ int sm[256];
    int t = threadIdx.x;
    int v = (t < nb) ? g_bsum[t] : 0;
    sm[t] = v;
    __syncthreads();
#pragma unroll
    for (int o = 1; o < 256; o <<= 1) {
        int tv = (t >= o) ? sm[t - o] : 0;
        __syncthreads();
        sm[t] += tv;
        __syncthreads();
    }
    if (t < nb) g_bsum[t] = sm[t] - v;
}

__global__ void scan3_kernel(int n) {
    int i = blockIdx.x * blockDim.x + threadIdx.x;
    if (i < n) {
        int v = g_rowstart[i] + g_bsum[i >> 10];
        g_rowstart[i] = v;
        g_cursor[i]   = v;
    }
}

__global__ void fill_kernel(const int* __restrict__ src, const int* __restrict__ dst, int E) {
    int e = blockIdx.x * blockDim.x + threadIdx.x;
    if (e < E) {
        int p = atomicAdd(&g_cursor[dst[e]], 1);
        g_csr[p] = src[e];
    }
}

// ============ GEMM 1 (proven config): 128 rows/block, thread = 4 rows x 8 cols ============
__global__ void __launch_bounds__(256) gemm1_kernel(const float* __restrict__ x,
                                                    const float* __restrict__ W, int n) {
    extern __shared__ float sm[];
    float* wsa = sm;
    float* wsb = sm + 4096;
    float* xs  = sm + 8192;
    int tid = threadIdx.x;
    for (int i = tid; i < 128 * 64; i += 256) {
        int k = i >> 6, j = i & 63;
        float v = W[i];
        int jt = j >> 3, c = j & 7;
        if (c < 4) wsa[k * 32 + jt * 4 + c] = v;
        else       wsb[k * 32 + jt * 4 + (c - 4)] = v;
    }
    int row0 = blockIdx.x * 128;
    int lane = tid & 31, wrp = tid >> 5;
    int rg4 = (wrp * 4 + (lane >> 3)) * 4;
    int jt  = lane & 7;
    float acc[4][8];
#pragma unroll
    for (int i = 0; i < 4; i++)
#pragma unroll
        for (int j = 0; j < 8; j++) acc[i][j] = 0.f;

    int frow = tid >> 3;
    int kq   = tid & 7;
    int csw  = ((kq & 3) << 3) | ((kq >> 2) << 2);

    for (int kc = 0; kc < 4; kc++) {
        __syncthreads();
#pragma unroll
        for (int it = 0; it < 4; it++) {
            int row  = frow + it * 32;
            int grow = row0 + row;
            float4 v = (grow < n) ? *(const float4*)(x + (size_t)grow * 128 + kc * 32 + kq * 4)
                                  : make_float4(0.f, 0.f, 0.f, 0.f);
            int rs = row ^ csw;
            xs[(kq * 4 + 0) * 132 + rs] = v.x;
            xs[(kq * 4 + 1) * 132 + rs] = v.y;
            xs[(kq * 4 + 2) * 132 + rs] = v.z;
            xs[(kq * 4 + 3) * 132 + rs] = v.w;
        }
        __syncthreads();
#pragma unroll
        for (int kk = 0; kk < 32; kk++) {
            int c = (((kk >> 2) & 3) << 3) | (((kk >> 4) & 1) << 2);
            float4 xv = *(const float4*)(xs + kk * 132 + (rg4 ^ c));
            int k = kc * 32 + kk;
            float4 a = *(const float4*)(wsa + k * 32 + jt * 4);
            float4 b = *(const float4*)(wsb + k * 32 + jt * 4);
            float xr[4] = {xv.x, xv.y, xv.z, xv.w};
#pragma unroll
            for (int i = 0; i < 4; i++) {
                acc[i][0] = fmaf(xr[i], a.x, acc[i][0]);
                acc[i][1] = fmaf(xr[i], a.y, acc[i][1]);
                acc[i][2] = fmaf(xr[i], a.z, acc[i][2]);
                acc[i][3] = fmaf(xr[i], a.w, acc[i][3]);
                acc[i][4] = fmaf(xr[i], b.x, acc[i][4]);
                acc[i][5] = fmaf(xr[i], b.y, acc[i][5]);
                acc[i][6] = fmaf(xr[i], b.z, acc[i][6]);
                acc[i][7] = fmaf(xr[i], b.w, acc[i][7]);
            }
        }
    }
#pragma unroll
    for (int i = 0; i < 4; i++) {
        int rr = row0 + rg4 + i;
        if (rr < n) {
            float di = g_dis[rr];
            __half2* o = g_h0h + (size_t)rr * 32 + jt * 4;
            o[0] = __floats2half2_rn(di*acc[i][0], di*acc[i][1]);
            o[1] = __floats2half2_rn(di*acc[i][2], di*acc[i][3]);
            o[2] = __floats2half2_rn(di*acc[i][4], di*acc[i][5]);
            o[3] = __floats2half2_rn(di*acc[i][6], di*acc[i][7]);
        }
    }
}

// ====== GEMM 2 (proven config) ======
__global__ void __launch_bounds__(256) gemm2_kernel(const float* __restrict__ Wmu,
                                                    const float* __restrict__ Wls, int n) {
    extern __shared__ float sm[];
    float* wsa = sm;
    float* wsb = sm + 2048;
    float* xs  = sm + 4096;
    int tid = threadIdx.x;
    for (int i = tid; i < 64 * 64; i += 256) {
        int k = i >> 6, j = i & 63;
        float v = (j < 32) ? Wmu[k * 32 + j] : Wls[k * 32 + (j - 32)];
        int jn = (j < 32) ? (2 * j) : (2 * (j - 32) + 1);
        int jt = jn >> 3, c = jn & 7;
        if (c < 4) wsa[k * 32 + jt * 4 + c] = v;
        else       wsb[k * 32 + jt * 4 + (c - 4)] = v;
    }
    int row0 = blockIdx.x * 128;
    int lane = tid & 31, wrp = tid >> 5;
    int rg4 = (wrp * 4 + (lane >> 3)) * 4;
    int jt  = lane & 7;
    float acc[4][8];
#pragma unroll
    for (int i = 0; i < 4; i++)
#pragma unroll
        for (int j = 0; j < 8; j++) acc[i][j] = 0.f;

    int frow = tid >> 3;
    int kq   = tid & 7;
    int csw  = ((kq & 3) << 3) | ((kq >> 2) << 2);

    for (int kc = 0; kc < 2; kc++) {
        __syncthreads();
#pragma unroll
        for (int it = 0; it < 4; it++) {
            int row  = frow + it * 32;
            int grow = row0 + row;
            float4 v = (grow < n) ? *(const float4*)(g_h + (size_t)grow * 64 + kc * 32 + kq * 4)
                                  : make_float4(0.f, 0.f, 0.f, 0.f);
            int rs = row ^ csw;
            xs[(kq * 4 + 0) * 132 + rs] = v.x;
            xs[(kq * 4 + 1) * 132 + rs] = v.y;
            xs[(kq * 4 + 2) * 132 + rs] = v.z;
            xs[(kq * 4 + 3) * 132 + rs] = v.w;
        }
        __syncthreads();
#pragma unroll
        for (int kk = 0; kk < 32; kk++) {
            int c = (((kk >> 2) & 3) << 3) | (((kk >> 4) & 1) << 2);
            float4 xv = *(const float4*)(xs + kk * 132 + (rg4 ^ c));
            int k = kc * 32 + kk;
            float4 a = *(const float4*)(wsa + k * 32 + jt * 4);
            float4 b = *(const float4*)(wsb + k * 32 + jt * 4);
            float xr[4] = {xv.x, xv.y, xv.z, xv.w};
#pragma unroll
            for (int i = 0; i < 4; i++) {
                acc[i][0] = fmaf(xr[i], a.x, acc[i][0]);
                acc[i][1] = fmaf(xr[i], a.y, acc[i][1]);
                acc[i][2] = fmaf(xr[i], a.z, acc[i][2]);
                acc[i][3] = fmaf(xr[i], a.w, acc[i][3]);
                acc[i][4] = fmaf(xr[i], b.x, acc[i][4]);
                acc[i][5] = fmaf(xr[i], b.y, acc[i][5]);
                acc[i][6] = fmaf(xr[i], b.z, acc[i][6]);
                acc[i][7] = fmaf(xr[i], b.w, acc[i][7]);
            }
        }
    }
#pragma unroll
    for (int i = 0; i < 4; i++) {
        int rr = row0 + rg4 + i;
        if (rr < n) {
            float di = g_dis[rr];
            __half2* o = g_ggh + (size_t)rr * 32 + jt * 4;
            o[0] = __floats2half2_rn(di*acc[i][0], di*acc[i][1]);
            o[1] = __floats2half2_rn(di*acc[i][2], di*acc[i][3]);
            o[2] = __floats2half2_rn(di*acc[i][4], di*acc[i][5]);
            o[3] = __floats2half2_rn(di*acc[i][6], di*acc[i][7]);
        }
    }
}

// -------- Conv1: half-warp/node, 8-edge unroll with pipelined index loads --------
__global__ void __launch_bounds__(256) conv1_kernel(const float* __restrict__ b1, int n) {
    int node = blockIdx.x * 16 + (threadIdx.x >> 4);
    int t    = threadIdx.x & 15;
    bool valid = node < n;
    int nd = valid ? node : 0;
    int st  = g_rowstart[nd];
    int cnt = valid ? g_indeg[nd] : 0;
    const int* cs = g_csr + st;
    const __half2* hb = g_h0h + 2 * t;
    float a0x=0.f,a0y=0.f,a0z=0.f,a0w=0.f, a1x=0.f,a1y=0.f,a1z=0.f,a1w=0.f;
    int e = 0;
    if (cnt >= 8) {
        int i0 = cs[0], i1 = cs[1], i2 = cs[2], i3 = cs[3];
        int i4 = cs[4], i5 = cs[5], i6 = cs[6], i7 = cs[7];
        for (;;) {
            uint2 u0 = *(const uint2*)(hb + (size_t)i0 * 32);
            uint2 u1 = *(const uint2*)(hb + (size_t)i1 * 32);
            uint2 u2 = *(const uint2*)(hb + (size_t)i2 * 32);
            uint2 u3 = *(const uint2*)(hb + (size_t)i3 * 32);
            uint2 u4 = *(const uint2*)(hb + (size_t)i4 * 32);
            uint2 u5 = *(const uint2*)(hb + (size_t)i5 * 32);
            uint2 u6 = *(const uint2*)(hb + (size_t)i6 * 32);
            uint2 u7 = *(const uint2*)(hb + (size_t)i7 * 32);
            e += 8;
            bool more = (e + 8 <= cnt);
            if (more) {
                i0 = cs[e];   i1 = cs[e+1]; i2 = cs[e+2]; i3 = cs[e+3];
                i4 = cs[e+4]; i5 = cs[e+5]; i6 = cs[e+6]; i7 = cs[e+7];
            }
            float2 p; 
            p = __half22float2(*(__half2*)&u0.x); a0x += p.x; a0y += p.y;
            p = __half22float2(*(__half2*)&u0.y); a0z += p.x; a0w += p.y;
            p = __half22float2(*(__half2*)&u1.x); a1x += p.x; a1y += p.y;
            p = __half22float2(*(__half2*)&u1.y); a1z += p.x; a1w += p.y;
            p = __half22float2(*(__half2*)&u2.x); a0x += p.x; a0y += p.y;
            p = __half22float2(*(__half2*)&u2.y); a0z += p.x; a0w += p.y;
            p = __half22float2(*(__half2*)&u3.x); a1x += p.x; a1y += p.y;
            p = __half22float2(*(__half2*)&u3.y); a1z += p.x; a1w += p.y;
            p = __half22float2(*(__half2*)&u4.x); a0x += p.x; a0y += p.y;
            p = __half22float2(*(__half2*)&u4.y); a0z += p.x; a0w += p.y;
            p = __half22float2(*(__half2*)&u5.x); a1x += p.x; a1y += p.y;
            p = __half22float2(*(__half2*)&u5.y); a1z += p.x; a1w += p.y;
            p = __half22float2(*(__half2*)&u6.x); a0x += p.x; a0y += p.y;
            p = __half22float2(*(__half2*)&u6.y); a0z += p.x; a0w += p.y;
            p = __half22float2(*(__half2*)&u7.x); a1x += p.x; a1y += p.y;
            p = __half22float2(*(__half2*)&u7.y); a1z += p.x; a1w += p.y;
            if (!more) break;
        }
    }
    for (; e < cnt; e++) {
        uint2 u = *(const uint2*)(hb + (size_t)cs[e] * 32);
        float2 p = __half22float2(*(__half2*)&u.x), q = __half22float2(*(__half2*)&u.y);
        a0x += p.x; a0y += p.y; a0z += q.x; a0w += q.y;
    }
    uint2 us = *(const uint2*)(hb + (size_t)nd * 32);
    float2 ps = __half22float2(*(__half2*)&us.x), qs = __half22float2(*(__half2*)&us.y);
    float sx = a0x + a1x + ps.x;
    float sy = a0y + a1y + ps.y;
    float sz = a0z + a1z + qs.x;
    float sw = a0w + a1w + qs.y;
    float di = g_dis[nd];
    float4 bb = *(const float4*)(b1 + 4 * t);
    float vx = fmaxf(fmaf(di, sx, bb.x), 0.f);
    float vy = fmaxf(fmaf(di, sy, bb.y), 0.f);
    float vz = fmaxf(fmaf(di, sz, bb.z), 0.f);
    float vw = fmaxf(fmaf(di, sw, bb.w), 0.f);
    float ss = vx*vx + vy*vy + vz*vz + vw*vw;
#pragma unroll
    for (int o = 8; o > 0; o >>= 1) ss += __shfl_xor_sync(0xffffffffu, ss, o);
    float scale = 1.0f / fmaxf(sqrtf(ss), 1e-12f);
    if (valid)
        *(float4*)(g_h + (size_t)nd * 64 + 4 * t) =
            make_float4(vx*scale, vy*scale, vz*scale, vw*scale);
}

// -------- Conv2 + reparametrize: half-warp/node, 8-edge pipelined unroll --------
__global__ void __launch_bounds__(256) conv2_kernel(const float* __restrict__ bmu,
                                                    const float* __restrict__ bls,
                                                    const float* __restrict__ eps,
                                                    float* __restrict__ out_mu,
                                                    float* __restrict__ out_ls, int n) {
    int node = blockIdx.x * 16 + (threadIdx.x >> 4);
    int t    = threadIdx.x & 15;
    bool valid = node < n;
    int nd = valid ? node : 0;
    int st  = g_rowstart[nd];
    int cnt = valid ? g_indeg[nd] : 0;
    const int* cs = g_csr + st;
    const __half2* gb = g_ggh + 2 * t;
    float a0x=0.f,a0y=0.f,a0z=0.f,a0w=0.f, a1x=0.f,a1y=0.f,a1z=0.f,a1w=0.f;
    int e = 0;
    if (cnt >= 8) {
        int i0 = cs[0], i1 = cs[1], i2 = cs[2], i3 = cs[3];
        int i4 = cs[4], i5 = cs[5], i6 = cs[6], i7 = cs[7];
        for (;;) {
            uint2 u0 = *(const uint2*)(gb + (size_t)i0 * 32);
            uint2 u1 = *(const uint2*)(gb + (size_t)i1 * 32);
            uint2 u2 = *(const uint2*)(gb + (size_t)i2 * 32);
            uint2 u3 = *(const uint2*)(gb + (size_t)i3 * 32);
            uint2 u4 = *(const uint2*)(gb + (size_t)i4 * 32);
            uint2 u5 = *(const uint2*)(gb + (size_t)i5 * 32);
            uint2 u6 = *(const uint2*)(gb + (size_t)i6 * 32);
            uint2 u7 = *(const uint2*)(gb + (size_t)i7 * 32);
            e += 8;
            bool more = (e + 8 <= cnt);
            if (more) {
                i0 = cs[e];   i1 = cs[e+1]; i2 = cs[e+2]; i3 = cs[e+3];
                i4 = cs[e+4]; i5 = cs[e+5]; i6 = cs[e+6]; i7 = cs[e+7];
            }
            float2 p;
            p = __half22float2(*(__half2*)&u0.x); a0x += p.x; a0y += p.y;
            p = __half22float2(*(__half2*)&u0.y); a0z += p.x; a0w += p.y;
            p = __half22float2(*(__half2*)&u1.x); a1x += p.x; a1y += p.y;
            p = __half22float2(*(__half2*)&u1.y); a1z += p.x; a1w += p.y;
            p = __half22float2(*(__half2*)&u2.x); a0x += p.x; a0y += p.y;
            p = __half22float2(*(__half2*)&u2.y); a0z += p.x; a0w += p.y;
            p = __half22float2(*(__half2*)&u3.x); a1x += p.x; a1y += p.y;
            p = __half22float2(*(__half2*)&u3.y); a1z += p.x; a1w += p.y;
            p = __half22float2(*(__half2*)&u4.x); a0x += p.x; a0y += p.y;
            p = __half22float2(*(__half2*)&u4.y); a0z += p.x; a0w += p.y;
            p = __half22float2(*(__half2*)&u5.x); a1x += p.x; a1y += p.y;
            p = __half22float2(*(__half2*)&u5.y); a1z += p.x; a1w += p.y;
            p = __half22float2(*(__half2*)&u6.x); a0x += p.x; a0y += p.y;
            p = __half22float2(*(__half2*)&u6.y); a0z += p.x; a0w += p.y;
            p = __half22float2(*(__half2*)&u7.x); a1x += p.x; a1y += p.y;
            p = __half22float2(*(__half2*)&u7.y); a1z += p.x; a1w += p.y;
            if (!more) break;
        }
    }
    for (; e < cnt; e++) {
        uint2 u = *(const uint2*)(gb + (size_t)cs[e] * 32);
        float2 p = __half22float2(*(__half2*)&u.x), q = __half22float2(*(__half2*)&u.y);
        a0x += p.x; a0y += p.y; a0z += q.x; a0w += q.y;
    }
    if (!valid) return;
    uint2 us = *(const uint2*)(gb + (size_t)nd * 32);
    float2 ps = __half22float2(*(__half2*)&us.x), qs = __half22float2(*(__half2*)&us.y);
    float di = g_dis[nd];
    float mu0 = fmaf(di, a0x + a1x + ps.x, bmu[2*t]);
    float ls0 = fmaf(di, a0y + a1y + ps.y, bls[2*t]);
    float mu1 = fmaf(di, a0z + a1z + qs.x, bmu[2*t+1]);
    float ls1 = fmaf(di, a0w + a1w + qs.y, bls[2*t+1]);
    size_t oi = (size_t)nd * 32 + 2*t;
    *(float2*)(out_mu + oi) = make_float2(mu0, mu1);
    *(float2*)(out_ls + oi) = make_float2(ls0, ls1);
    float2 ep = *(const float2*)(eps + oi);
    float lc0 = fminf(fmaxf(ls0, -10.f), 10.f);
    float lc1 = fminf(fmaxf(ls1, -10.f), 10.f);
    float z0 = fmaf(ep.x, __expf(lc0), mu0);
    float z1 = fmaf(ep.y, __expf(lc1), mu1);
    *(__half2*)(g_zh + oi) = __floats2half2_rn(z0, z1);
}

// ---------------- decode: 4 lanes/edge, uint4 (16B) loads ----------------
__global__ void __launch_bounds__(256) decode_kernel(const int* __restrict__ src,
                                                     const int* __restrict__ dst,
                                                     float* __restrict__ out, int E) {
    int gid = blockIdx.x * 256 + threadIdx.x;
    int e   = gid >> 2;
    int sub = gid & 3;
    if (e >= E) return;
    int s = src[e], d = dst[e];
    uint4 ua = *(const uint4*)(g_zh + (size_t)s * 32 + sub * 8);
    uint4 ub = *(const uint4*)(g_zh + (size_t)d * 32 + sub * 8);
    float2 a0 = __half22float2(*reinterpret_cast<__half2*>(&ua.x));
    float2 a1 = __half22float2(*reinterpret_cast<__half2*>(&ua.y));
    float2 a2 = __half22float2(*reinterpret_cast<__half2*>(&ua.z));
    float2 a3 = __half22float2(*reinterpret_cast<__half2*>(&ua.w));
    float2 b0 = __half22float2(*reinterpret_cast<__half2*>(&ub.x));
    float2 b1 = __half22float2(*reinterpret_cast<__half2*>(&ub.y));
    float2 b2 = __half22float2(*reinterpret_cast<__half2*>(&ub.z));
    float2 b3 = __half22float2(*reinterpret_cast<__half2*>(&ub.w));
    float p = a0.x*b0.x + a0.y*b0.y + a1.x*b1.x + a1.y*b1.y
            + a2.x*b2.x + a2.y*b2.y + a3.x*b3.x + a3.y*b3.y;
    p += __shfl_xor_sync(0xffffffffu, p, 1);
    p += __shfl_xor_sync(0xffffffffu, p, 2);
    if (sub == 0) out[e] = 1.0f / (1.0f + __expf(-p));
}

// ---------------- launch ----------------
extern "C" void kernel_launch(void* const* d_in, const int* in_sizes, int n_in,
                              void* d_out, int out_size) {
    const float* x   = (const float*)d_in[0];
    const int*   ei  = (const int*)  d_in[1];
    const float* eps = (const float*)d_in[2];
    const float* W1  = (const float*)d_in[3];
    const float* b1  = (const float*)d_in[4];
    const float* Wmu = (const float*)d_in[5];
    const float* bmu = (const float*)d_in[6];
    const float* Wls = (const float*)d_in[7];
    const float* bls = (const float*)d_in[8];

    int n = in_sizes[0] / 128;
    int E = in_sizes[1] / 2;
    const int* src = ei;
    const int* dst = ei + E;

    float* out     = (float*)d_out;
    float* out_adj = out;
    float* out_mu  = out + E;
    float* out_ls  = out + E + (size_t)n * 32;

    const int SMEM1 = (4096 + 4096 + 32 * 132) * 4;   // 49664
    const int SMEM2 = (2048 + 2048 + 32 * 132) * 4;   // 33280
    cudaFuncSetAttribute(gemm1_kernel, cudaFuncAttributeMaxDynamicSharedMemorySize, SMEM1);
    cudaFuncSetAttribute(gemm2_kernel, cudaFuncAttributeMaxDynamicSharedMemorySize, SMEM2);

    cudaStream_t s2;
    cudaEvent_t evFork, evJoin;
    cudaStreamCreateWithFlags(&s2, cudaStreamNonBlocking);
    cudaEventCreateWithFlags(&evFork, cudaEventDisableTiming);
    cudaEventCreateWithFlags(&evJoin, cudaEventDisableTiming);

    init_kernel<<<(n + 255) / 256, 256>>>(n);
    hist_kernel<<<(E + 255) / 256, 256>>>(dst, E);
    dis_kernel<<<(n + 255) / 256, 256>>>(n);

    // fork: gemm1 depends only on {x, W1, dis}
    cudaEventRecord(evFork, 0);
    cudaStreamWaitEvent(s2, evFork, 0);
    gemm1_kernel<<<(n + 127) / 128, 256, SMEM1, s2>>>(x, W1, n);
    cudaEventRecord(evJoin, s2);

    int nb = (n + 1023) / 1024;
    scan1_kernel<<<nb, 1024>>>(n);
    scan2_kernel<<<1, 256>>>(nb);
    scan3_kernel<<<(n + 255) / 256, 256>>>(n);
    fill_kernel<<<(E + 255) / 256, 256>>>(src, dst, E);

    cudaStreamWaitEvent(0, evJoin, 0);

    conv1_kernel<<<(n + 15) / 16, 256>>>(b1, n);
    gemm2_kernel<<<(n + 127) / 128, 256, SMEM2>>>(Wmu, Wls, n);
    conv2_kernel<<<(n + 15) / 16, 256>>>(bmu, bls, eps, out_mu, out_ls, n);
    decode_kernel<<<((size_t)E * 4 + 255) / 256, 256>>>(src, dst, out_adj, E);
}

// round 14
// speedup vs baseline: 1.0083x; 1.0083x over previous
#include <cuda_runtime.h>
#include <cuda_fp16.h>
#include <math.h>

#define MAXN 100000
#define MAXE 1600000

// ---------------- scratch ----------------
__device__ int     g_indeg[MAXN];
__device__ int     g_rowstart[MAXN];
__device__ int     g_cursor[MAXN];
__device__ int     g_bsum[256];
__device__ float   g_dis[MAXN];
__device__ int     g_csr[MAXE];
__device__ __half2 g_h0h[(size_t)MAXN * 32];    // fp16 x@W1 (prescaled by dis in scale_kernel)
__device__ float   g_h [(size_t)MAXN * 64];     // fp32 normalized hidden
__device__ __half2 g_ggh[(size_t)MAXN * 32];    // fp16 dis-prescaled (mu,ls) interleaved
__device__ __half  g_zh [(size_t)MAXN * 32];    // fp16 z

// ---------------- graph preprocessing ----------------
__global__ void init_kernel(int n) {
    int i = blockIdx.x * blockDim.x + threadIdx.x;
    if (i < n) g_indeg[i] = 0;
}

__global__ void hist_kernel(const int* __restrict__ dst, int E) {
    int e = blockIdx.x * blockDim.x + threadIdx.x;
    if (e < E) atomicAdd(&g_indeg[dst[e]], 1);
}

__global__ void dis_kernel(int n) {
    int i = blockIdx.x * blockDim.x + threadIdx.x;
    if (i < n) g_dis[i] = rsqrtf((float)(g_indeg[i] + 1));
}

// prescale unscaled gemm1 output by dis[row] (runs after gemm1 AND dis)
__global__ void scale_kernel(int n) {
    int i = blockIdx.x * blockDim.x + threadIdx.x;
    if (i < n * 32) {
        float di = g_dis[i >> 5];
        float2 v = __half22float2(g_h0h[i]);
        g_h0h[i] = __floats2half2_rn(v.x * di, v.y * di);
    }
}

__global__ void scan1_kernel(int n) {
    __shared__ int sm[1024];
    int t = threadIdx.x;
    int i = blockIdx.x * 1024 + t;
    int v = (i < n) ? g_indeg[i] : 0;
    sm[t] = v;
    __syncthreads();
#pragma unroll
    for (int o = 1; o < 1024; o <<= 1) {
        int tv = (t >= o) ? sm[t - o] : 0;
        __syncthreads();
        sm[t] += tv;
        __syncthreads();
    }
    if (i < n) g_rowstart[i] = sm[t] - v;
    if (t == 1023) g_bsum[blockIdx.x] = sm[1023];
}

__global__ void scan2_kernel(int nb) {
    __shared__ int sm[256];
    int t = threadIdx.x;
    int v = (t < nb) ? g_bsum[t] : 0;
    sm[t] = v;
    __syncthreads();
#pragma unroll
    for (int o = 1; o < 256; o <<= 1) {
        int tv = (t >= o) ? sm[t - o] : 0;
        __syncthreads();
        sm[t] += tv;
        __syncthreads();
    }
    if (t < nb) g_bsum[t] = sm[t] - v;
}

__global__ void scan3_kernel(int n) {
    int i = blockIdx.x * blockDim.x + threadIdx.x;
    if (i < n) {
        int v = g_rowstart[i] + g_bsum[i >> 10];
        g_rowstart[i] = v;
        g_cursor[i]   = v;
    }
}

__global__ void fill_kernel(const int* __restrict__ src, const int* __restrict__ dst, int E) {
    int e = blockIdx.x * blockDim.x + threadIdx.x;
    if (e < E) {
        int p = atomicAdd(&g_cursor[dst[e]], 1);
        g_csr[p] = src[e];
    }
}

// ============ GEMM 1: h0h = fp16(x @ W1) — UNSCALED (dis applied later) ============
__global__ void __launch_bounds__(256) gemm1_kernel(const float* __restrict__ x,
                                                    const float* __restrict__ W, int n) {
    extern __shared__ float sm[];
    float* wsa = sm;
    float* wsb = sm + 4096;
    float* xs  = sm + 8192;
    int tid = threadIdx.x;
    for (int i = tid; i < 128 * 64; i += 256) {
        int k = i >> 6, j = i & 63;
        float v = W[i];
        int jt = j >> 3, c = j & 7;
        if (c < 4) wsa[k * 32 + jt * 4 + c] = v;
        else       wsb[k * 32 + jt * 4 + (c - 4)] = v;
    }
    int row0 = blockIdx.x * 128;
    int lane = tid & 31, wrp = tid >> 5;
    int rg4 = (wrp * 4 + (lane >> 3)) * 4;
    int jt  = lane & 7;
    float acc[4][8];
#pragma unroll
    for (int i = 0; i < 4; i++)
#pragma unroll
        for (int j = 0; j < 8; j++) acc[i][j] = 0.f;

    int frow = tid >> 3;
    int kq   = tid & 7;
    int csw  = ((kq & 3) << 3) | ((kq >> 2) << 2);

    for (int kc = 0; kc < 4; kc++) {
        __syncthreads();
#pragma unroll
        for (int it = 0; it < 4; it++) {
            int row  = frow + it * 32;
            int grow = row0 + row;
            float4 v = (grow < n) ? *(const float4*)(x + (size_t)grow * 128 + kc * 32 + kq * 4)
                                  : make_float4(0.f, 0.f, 0.f, 0.f);
            int rs = row ^ csw;
            xs[(kq * 4 + 0) * 132 + rs] = v.x;
            xs[(kq * 4 + 1) * 132 + rs] = v.y;
            xs[(kq * 4 + 2) * 132 + rs] = v.z;
            xs[(kq * 4 + 3) * 132 + rs] = v.w;
        }
        __syncthreads();
#pragma unroll
        for (int kk = 0; kk < 32; kk++) {
            int c = (((kk >> 2) & 3) << 3) | (((kk >> 4) & 1) << 2);
            float4 xv = *(const float4*)(xs + kk * 132 + (rg4 ^ c));
            int k = kc * 32 + kk;
            float4 a = *(const float4*)(wsa + k * 32 + jt * 4);
            float4 b = *(const float4*)(wsb + k * 32 + jt * 4);
            float xr[4] = {xv.x, xv.y, xv.z, xv.w};
#pragma unroll
            for (int i = 0; i < 4; i++) {
                acc[i][0] = fmaf(xr[i], a.x, acc[i][0]);
                acc[i][1] = fmaf(xr[i], a.y, acc[i][1]);
                acc[i][2] = fmaf(xr[i], a.z, acc[i][2]);
                acc[i][3] = fmaf(xr[i], a.w, acc[i][3]);
                acc[i][4] = fmaf(xr[i], b.x, acc[i][4]);
                acc[i][5] = fmaf(xr[i], b.y, acc[i][5]);
                acc[i][6] = fmaf(xr[i], b.z, acc[i][6]);
                acc[i][7] = fmaf(xr[i], b.w, acc[i][7]);
            }
        }
    }
#pragma unroll
    for (int i = 0; i < 4; i++) {
        int rr = row0 + rg4 + i;
        if (rr < n) {
            __half2* o = g_h0h + (size_t)rr * 32 + jt * 4;
            o[0] = __floats2half2_rn(acc[i][0], acc[i][1]);
            o[1] = __floats2half2_rn(acc[i][2], acc[i][3]);
            o[2] = __floats2half2_rn(acc[i][4], acc[i][5]);
            o[3] = __floats2half2_rn(acc[i][6], acc[i][7]);
        }
    }
}

// ====== GEMM 2 (proven config): gg = fp16(dis[row] * (h @ interleave(Wmu,Wls))) ======
__global__ void __launch_bounds__(256) gemm2_kernel(const float* __restrict__ Wmu,
                                                    const float* __restrict__ Wls, int n) {
    extern __shared__ float sm[];
    float* wsa = sm;
    float* wsb = sm + 2048;
    float* xs  = sm + 4096;
    int tid = threadIdx.x;
    for (int i = tid; i < 64 * 64; i += 256) {
        int k = i >> 6, j = i & 63;
        float v = (j < 32) ? Wmu[k * 32 + j] : Wls[k * 32 + (j - 32)];
        int jn = (j < 32) ? (2 * j) : (2 * (j - 32) + 1);
        int jt = jn >> 3, c = jn & 7;
        if (c < 4) wsa[k * 32 + jt * 4 + c] = v;
        else       wsb[k * 32 + jt * 4 + (c - 4)] = v;
    }
    int row0 = blockIdx.x * 128;
    int lane = tid & 31, wrp = tid >> 5;
    int rg4 = (wrp * 4 + (lane >> 3)) * 4;
    int jt  = lane & 7;
    float acc[4][8];
#pragma unroll
    for (int i = 0; i < 4; i++)
#pragma unroll
        for (int j = 0; j < 8; j++) acc[i][j] = 0.f;

    int frow = tid >> 3;
    int kq   = tid & 7;
    int csw  = ((kq & 3) << 3) | ((kq >> 2) << 2);

    for (int kc = 0; kc < 2; kc++) {
        __syncthreads();
#pragma unroll
        for (int it = 0; it < 4; it++) {
            int row  = frow + it * 32;
            int grow = row0 + row;
            float4 v = (grow < n) ? *(const float4*)(g_h + (size_t)grow * 64 + kc * 32 + kq * 4)
                                  : make_float4(0.f, 0.f, 0.f, 0.f);
            int rs = row ^ csw;
            xs[(kq * 4 + 0) * 132 + rs] = v.x;
            xs[(kq * 4 + 1) * 132 + rs] = v.y;
            xs[(kq * 4 + 2) * 132 + rs] = v.z;
            xs[(kq * 4 + 3) * 132 + rs] = v.w;
        }
        __syncthreads();
#pragma unroll
        for (int kk = 0; kk < 32; kk++) {
            int c = (((kk >> 2) & 3) << 3) | (((kk >> 4) & 1) << 2);
            float4 xv = *(const float4*)(xs + kk * 132 + (rg4 ^ c));
            int k = kc * 32 + kk;
            float4 a = *(const float4*)(wsa + k * 32 + jt * 4);
            float4 b = *(const float4*)(wsb + k * 32 + jt * 4);
            float xr[4] = {xv.x, xv.y, xv.z, xv.w};
#pragma unroll
            for (int i = 0; i < 4; i++) {
                acc[i][0] = fmaf(xr[i], a.x, acc[i][0]);
                acc[i][1] = fmaf(xr[i], a.y, acc[i][1]);
                acc[i][2] = fmaf(xr[i], a.z, acc[i][2]);
                acc[i][3] = fmaf(xr[i], a.w, acc[i][3]);
                acc[i][4] = fmaf(xr[i], b.x, acc[i][4]);
                acc[i][5] = fmaf(xr[i], b.y, acc[i][5]);
                acc[i][6] = fmaf(xr[i], b.z, acc[i][6]);
                acc[i][7] = fmaf(xr[i], b.w, acc[i][7]);
            }
        }
    }
#pragma unroll
    for (int i = 0; i < 4; i++) {
        int rr = row0 + rg4 + i;
        if (rr < n) {
            float di = g_dis[rr];
            __half2* o = g_ggh + (size_t)rr * 32 + jt * 4;
            o[0] = __floats2half2_rn(di*acc[i][0], di*acc[i][1]);
            o[1] = __floats2half2_rn(di*acc[i][2], di*acc[i][3]);
            o[2] = __floats2half2_rn(di*acc[i][4], di*acc[i][5]);
            o[3] = __floats2half2_rn(di*acc[i][6], di*acc[i][7]);
        }
    }
}

// -------- Conv1 (R12 config): half-warp/node, 4-edge unroll --------
__global__ void __launch_bounds__(256) conv1_kernel(const float* __restrict__ b1, int n) {
    int node = blockIdx.x * 16 + (threadIdx.x >> 4);
    int t    = threadIdx.x & 15;
    bool valid = node < n;
    int nd = valid ? node : 0;
    int st  = g_rowstart[nd];
    int cnt = valid ? g_indeg[nd] : 0;
    const int* cs = g_csr + st;
    const __half2* hb = g_h0h + 2 * t;
    float a0x=0.f,a0y=0.f,a0z=0.f,a0w=0.f, a1x=0.f,a1y=0.f,a1z=0.f,a1w=0.f;
    int e = 0;
    for (; e + 4 <= cnt; e += 4) {
        int s0 = cs[e], s1 = cs[e+1], s2 = cs[e+2], s3 = cs[e+3];
        uint2 u0 = *(const uint2*)(hb + (size_t)s0 * 32);
        uint2 u1 = *(const uint2*)(hb + (size_t)s1 * 32);
        uint2 u2 = *(const uint2*)(hb + (size_t)s2 * 32);
        uint2 u3 = *(const uint2*)(hb + (size_t)s3 * 32);
        float2 p0 = __half22float2(*(__half2*)&u0.x), q0 = __half22float2(*(__half2*)&u0.y);
        float2 p1 = __half22float2(*(__half2*)&u1.x), q1 = __half22float2(*(__half2*)&u1.y);
        float2 p2 = __half22float2(*(__half2*)&u2.x), q2 = __half22float2(*(__half2*)&u2.y);
        float2 p3 = __half22float2(*(__half2*)&u3.x), q3 = __half22float2(*(__half2*)&u3.y);
        a0x += p0.x; a0y += p0.y; a0z += q0.x; a0w += q0.y;
        a1x += p1.x; a1y += p1.y; a1z += q1.x; a1w += q1.y;
        a0x += p2.x; a0y += p2.y; a0z += q2.x; a0w += q2.y;
        a1x += p3.x; a1y += p3.y; a1z += q3.x; a1w += q3.y;
    }
    for (; e < cnt; e++) {
        uint2 u = *(const uint2*)(hb + (size_t)cs[e] * 32);
        float2 p = __half22float2(*(__half2*)&u.x), q = __half22float2(*(__half2*)&u.y);
        a0x += p.x; a0y += p.y; a0z += q.x; a0w += q.y;
    }
    uint2 us = *(const uint2*)(hb + (size_t)nd * 32);
    float2 ps = __half22float2(*(__half2*)&us.x), qs = __half22float2(*(__half2*)&us.y);
    float sx = a0x + a1x + ps.x;
    float sy = a0y + a1y + ps.y;
    float sz = a0z + a1z + qs.x;
    float sw = a0w + a1w + qs.y;
    float di = g_dis[nd];
    float4 bb = *(const float4*)(b1 + 4 * t);
    float vx = fmaxf(fmaf(di, sx, bb.x), 0.f);
    float vy = fmaxf(fmaf(di, sy, bb.y), 0.f);
    float vz = fmaxf(fmaf(di, sz, bb.z), 0.f);
    float vw = fmaxf(fmaf(di, sw, bb.w), 0.f);
    float ss = vx*vx + vy*vy + vz*vz + vw*vw;
#pragma unroll
    for (int o = 8; o > 0; o >>= 1) ss += __shfl_xor_sync(0xffffffffu, ss, o);
    float scale = 1.0f / fmaxf(sqrtf(ss), 1e-12f);
    if (valid)
        *(float4*)(g_h + (size_t)nd * 64 + 4 * t) =
            make_float4(vx*scale, vy*scale, vz*scale, vw*scale);
}

// -------- Conv2 + reparametrize (R12 config) --------
__global__ void __launch_bounds__(256) conv2_kernel(const float* __restrict__ bmu,
                                                    const float* __restrict__ bls,
                                                    const float* __restrict__ eps,
                                                    float* __restrict__ out_mu,
                                                    float* __restrict__ out_ls, int n) {
    int node = blockIdx.x * 16 + (threadIdx.x >> 4);
    int t    = threadIdx.x & 15;
    bool valid = node < n;
    int nd = valid ? node : 0;
    int st  = g_rowstart[nd];
    int cnt = valid ? g_indeg[nd] : 0;
    const int* cs = g_csr + st;
    const __half2* gb = g_ggh + 2 * t;
    float a0x=0.f,a0y=0.f,a0z=0.f,a0w=0.f, a1x=0.f,a1y=0.f,a1z=0.f,a1w=0.f;
    int e = 0;
    for (; e + 4 <= cnt; e += 4) {
        int s0 = cs[e], s1 = cs[e+1], s2 = cs[e+2], s3 = cs[e+3];
        uint2 u0 = *(const uint2*)(gb + (size_t)s0 * 32);
        uint2 u1 = *(const uint2*)(gb + (size_t)s1 * 32);
        uint2 u2 = *(const uint2*)(gb + (size_t)s2 * 32);
        uint2 u3 = *(const uint2*)(gb + (size_t)s3 * 32);
        float2 p0 = __half22float2(*(__half2*)&u0.x), q0 = __half22float2(*(__half2*)&u0.y);
        float2 p1 = __half22float2(*(__half2*)&u1.x), q1 = __half22float2(*(__half2*)&u1.y);
        float2 p2 = __half22float2(*(__half2*)&u2.x), q2 = __half22float2(*(__half2*)&u2.y);
        float2 p3 = __half22float2(*(__half2*)&u3.x), q3 = __half22float2(*(__half2*)&u3.y);
        a0x += p0.x; a0y += p0.y; a0z += q0.x; a0w += q0.y;
        a1x += p1.x; a1y += p1.y; a1z += q1.x; a1w += q1.y;
        a0x += p2.x; a0y += p2.y; a0z += q2.x; a0w += q2.y;
        a1x += p3.x; a1y += p3.y; a1z += q3.x; a1w += q3.y;
    }
    for (; e < cnt; e++) {
        uint2 u = *(const uint2*)(gb + (size_t)cs[e] * 32);
        float2 p = __half22float2(*(__half2*)&u.x), q = __half22float2(*(__half2*)&u.y);
        a0x += p.x; a0y += p.y; a0z += q.x; a0w += q.y;
    }
    if (!valid) return;
    uint2 us = *(const uint2*)(gb + (size_t)nd * 32);
    float2 ps = __half22float2(*(__half2*)&us.x), qs = __half22float2(*(__half2*)&us.y);
    float di = g_dis[nd];
    float mu0 = fmaf(di, a0x + a1x + ps.x, bmu[2*t]);
    float ls0 = fmaf(di, a0y + a1y + ps.y, bls[2*t]);
    float mu1 = fmaf(di, a0z + a1z + qs.x, bmu[2*t+1]);
    float ls1 = fmaf(di, a0w + a1w + qs.y, bls[2*t+1]);
    size_t oi = (size_t)nd * 32 + 2*t;
    *(float2*)(out_mu + oi) = make_float2(mu0, mu1);
    *(float2*)(out_ls + oi) = make_float2(ls0, ls1);
    float2 ep = *(const float2*)(eps + oi);
    float lc0 = fminf(fmaxf(ls0, -10.f), 10.f);
    float lc1 = fminf(fmaxf(ls1, -10.f), 10.f);
    float z0 = fmaf(ep.x, __expf(lc0), mu0);
    float z1 = fmaf(ep.y, __expf(lc1), mu1);
    *(__half2*)(g_zh + oi) = __floats2half2_rn(z0, z1);
}

// ---------------- decode: 4 lanes/edge, uint4 (16B) loads ----------------
__global__ void __launch_bounds__(256) decode_kernel(const int* __restrict__ src,
                                                     const int* __restrict__ dst,
                                                     float* __restrict__ out, int E) {
    int gid = blockIdx.x * 256 + threadIdx.x;
    int e   = gid >> 2;
    int sub = gid & 3;
    if (e >= E) return;
    int s = src[e], d = dst[e];
    uint4 ua = *(const uint4*)(g_zh + (size_t)s * 32 + sub * 8);
    uint4 ub = *(const uint4*)(g_zh + (size_t)d * 32 + sub * 8);
    float2 a0 = __half22float2(*reinterpret_cast<__half2*>(&ua.x));
    float2 a1 = __half22float2(*reinterpret_cast<__half2*>(&ua.y));
    float2 a2 = __half22float2(*reinterpret_cast<__half2*>(&ua.z));
    float2 a3 = __half22float2(*reinterpret_cast<__half2*>(&ua.w));
    float2 b0 = __half22float2(*reinterpret_cast<__half2*>(&ub.x));
    float2 b1 = __half22float2(*reinterpret_cast<__half2*>(&ub.y));
    float2 b2 = __half22float2(*reinterpret_cast<__half2*>(&ub.z));
    float2 b3 = __half22float2(*reinterpret_cast<__half2*>(&ub.w));
    float p = a0.x*b0.x + a0.y*b0.y + a1.x*b1.x + a1.y*b1.y
            + a2.x*b2.x + a2.y*b2.y + a3.x*b3.x + a3.y*b3.y;
    p += __shfl_xor_sync(0xffffffffu, p, 1);
    p += __shfl_xor_sync(0xffffffffu, p, 2);
    if (sub == 0) out[e] = 1.0f / (1.0f + __expf(-p));
}

// ---------------- launch ----------------
extern "C" void kernel_launch(void* const* d_in, const int* in_sizes, int n_in,
                              void* d_out, int out_size) {
    const float* x   = (const float*)d_in[0];
    const int*   ei  = (const int*)  d_in[1];
    const float* eps = (const float*)d_in[2];
    const float* W1  = (const float*)d_in[3];
    const float* b1  = (const float*)d_in[4];
    const float* Wmu = (const float*)d_in[5];
    const float* bmu = (const float*)d_in[6];
    const float* Wls = (const float*)d_in[7];
    const float* bls = (const float*)d_in[8];

    int n = in_sizes[0] / 128;
    int E = in_sizes[1] / 2;
    const int* src = ei;
    const int* dst = ei + E;

    float* out     = (float*)d_out;
    float* out_adj = out;
    float* out_mu  = out + E;
    float* out_ls  = out + E + (size_t)n * 32;

    const int SMEM1 = (4096 + 4096 + 32 * 132) * 4;   // 49664
    const int SMEM2 = (2048 + 2048 + 32 * 132) * 4;   // 33280
    cudaFuncSetAttribute(gemm1_kernel, cudaFuncAttributeMaxDynamicSharedMemorySize, SMEM1);
    cudaFuncSetAttribute(gemm2_kernel, cudaFuncAttributeMaxDynamicSharedMemorySize, SMEM2);

    cudaStream_t s2;
    cudaEvent_t evFork, evDis, evJoin;
    cudaStreamCreateWithFlags(&s2, cudaStreamNonBlocking);
    cudaEventCreateWithFlags(&evFork, cudaEventDisableTiming);
    cudaEventCreateWithFlags(&evDis,  cudaEventDisableTiming);
    cudaEventCreateWithFlags(&evJoin, cudaEventDisableTiming);

    // fork at t=0: gemm1 (unscaled) needs only {x, W1}
    cudaEventRecord(evFork, 0);
    cudaStreamWaitEvent(s2, evFork, 0);
    gemm1_kernel<<<(n + 127) / 128, 256, SMEM1, s2>>>(x, W1, n);

    // main stream: degree histogram + dis + CSR build
    init_kernel<<<(n + 255) / 256, 256>>>(n);
    hist_kernel<<<(E + 255) / 256, 256>>>(dst, E);
    dis_kernel<<<(n + 255) / 256, 256>>>(n);
    cudaEventRecord(evDis, 0);

    int nb = (n + 1023) / 1024;
    scan1_kernel<<<nb, 1024>>>(n);
    scan2_kernel<<<1, 256>>>(nb);
    scan3_kernel<<<(n + 255) / 256, 256>>>(n);
    fill_kernel<<<(E + 255) / 256, 256>>>(src, dst, E);

    // s2: prescale h0h once gemm1 (in-order on s2) and dis (evDis) are done
    cudaStreamWaitEvent(s2, evDis, 0);
    scale_kernel<<<(n * 32 + 255) / 256, 256, 0, s2>>>(n);
    cudaEventRecord(evJoin, s2);

    // join: conv1 needs CSR + scaled h0h
    cudaStreamWaitEvent(0, evJoin, 0);

    conv1_kernel<<<(n + 15) / 16, 256>>>(b1, n);
    gemm2_kernel<<<(n + 127) / 128, 256, SMEM2>>>(Wmu, Wls, n);
    conv2_kernel<<<(n + 15) / 16, 256>>>(bmu, bls, eps, out_mu, out_ls, n);
    decode_kernel<<<((size_t)E * 4 + 255) / 256, 256>>>(src, dst, out_adj, E);
}

// round 15
// speedup vs baseline: 1.0380x; 1.0295x over previous
#include <cuda_runtime.h>
#include <cuda_fp16.h>
#include <math.h>

#define MAXN 100000
#define MAXE 1600000

// ---------------- scratch ----------------
__device__ int     g_indeg[MAXN];
__device__ int     g_rowstart[MAXN];
__device__ int     g_cursor[MAXN];
__device__ int     g_bsum[256];
__device__ float   g_dis[MAXN];
__device__ int     g_csr[MAXE];
__device__ __half2 g_h0h[(size_t)MAXN * 32];    // fp16 dis-prescaled x@W1
__device__ float   g_h [(size_t)MAXN * 64];     // fp32 normalized hidden
__device__ __half2 g_ggh[(size_t)MAXN * 32];    // fp16 dis-prescaled (mu,ls) interleaved
__device__ __half  g_zh [(size_t)MAXN * 32];    // fp16 z

// ---------------- graph preprocessing ----------------
__global__ void init_kernel(int n) {
    int i = blockIdx.x * blockDim.x + threadIdx.x;
    if (i < n) g_indeg[i] = 0;
}

__global__ void hist_kernel(const int* __restrict__ dst, int E) {
    int e = blockIdx.x * blockDim.x + threadIdx.x;
    if (e < E) atomicAdd(&g_indeg[dst[e]], 1);
}

__global__ void dis_kernel(int n) {
    int i = blockIdx.x * blockDim.x + threadIdx.x;
    if (i < n) g_dis[i] = rsqrtf((float)(g_indeg[i] + 1));
}

__global__ void scan1_kernel(int n) {
    __shared__ int sm[1024];
    int t = threadIdx.x;
    int i = blockIdx.x * 1024 + t;
    int v = (i < n) ? g_indeg[i] : 0;
    sm[t] = v;
    __syncthreads();
#pragma unroll
    for (int o = 1; o < 1024; o <<= 1) {
        int tv = (t >= o) ? sm[t - o] : 0;
        __syncthreads();
        sm[t] += tv;
        __syncthreads();
    }
    if (i < n) g_rowstart[i] = sm[t] - v;
    if (t == 1023) g_bsum[blockIdx.x] = sm[1023];
}

__global__ void scan2_kernel(int nb) {
    __shared__ int sm[256];
    int t = threadIdx.x;
    int v = (t < nb) ? g_bsum[t] : 0;
    sm[t] = v;
    __syncthreads();
#pragma unroll
    for (int o = 1; o < 256; o <<= 1) {
        int tv = (t >= o) ? sm[t - o] : 0;
        __syncthreads();
        sm[t] += tv;
        __syncthreads();
    }
    if (t < nb) g_bsum[t] = sm[t] - v;
}

__global__ void scan3_kernel(int n) {
    int i = blockIdx.x * blockDim.x + threadIdx.x;
    if (i < n) {
        int v = g_rowstart[i] + g_bsum[i >> 10];
        g_rowstart[i] = v;
        g_cursor[i]   = v;
    }
}

__global__ void fill_kernel(const int* __restrict__ src, const int* __restrict__ dst, int E) {
    int e = blockIdx.x * blockDim.x + threadIdx.x;
    if (e < E) {
        int p = atomicAdd(&g_cursor[dst[e]], 1);
        g_csr[p] = src[e];
    }
}

// ============ GEMM 1 (tensor cores): h0h = fp16(dis[row] * (x @ W1)) ============
// 64 rows x 64 cols per block, 8 warps, warp tile 32x16, mma.m16n8k16 f16.
// smem: xh [64][136] halves (x converted to fp16), wt [64][136] halves (W^T).
#define XSTR 136
__global__ void __launch_bounds__(256) gemm1_kernel(const float* __restrict__ x,
                                                    const float* __restrict__ W, int n) {
    __shared__ __half xh[64 * XSTR];
    __shared__ __half wt[64 * XSTR];
    int tid  = threadIdx.x;
    int row0 = blockIdx.x * 64;

    // stage x tile [64][128] fp32 -> fp16 (coalesced float2 loads)
    for (int i = tid; i < 64 * 64; i += 256) {
        int r = i >> 6, c2 = i & 63;          // c2 = half2 column
        int grow = row0 + r;
        float2 v = (grow < n) ? *(const float2*)(x + (size_t)grow * 128 + 2 * c2)
                              : make_float2(0.f, 0.f);
        *(__half2*)(xh + r * XSTR + 2 * c2) = __floats2half2_rn(v.x, v.y);
    }
    // stage W^T: wt[j][k] = W[k][j]  (coalesced float4 reads of W)
    for (int i = tid; i < 128 * 16; i += 256) {
        int k = i >> 4, f4 = i & 15;
        float4 wv = *(const float4*)(W + k * 64 + f4 * 4);
        int j0 = f4 * 4;
        wt[(j0 + 0) * XSTR + k] = __float2half_rn(wv.x);
        wt[(j0 + 1) * XSTR + k] = __float2half_rn(wv.y);
        wt[(j0 + 2) * XSTR + k] = __float2half_rn(wv.z);
        wt[(j0 + 3) * XSTR + k] = __float2half_rn(wv.w);
    }
    __syncthreads();

    int w    = tid >> 5;
    int lane = tid & 31;
    int gid  = lane >> 2;      // 0..7
    int q    = lane & 3;       // 0..3
    int Rb   = (w & 1) * 32;   // warp row base (32 rows)
    int Cb   = (w >> 1) * 16;  // warp col base (16 cols)

    float acc[2][2][4];        // [sm][sn][c0..c3]
#pragma unroll
    for (int a = 0; a < 2; a++)
#pragma unroll
        for (int b = 0; b < 2; b++)
#pragma unroll
            for (int c = 0; c < 4; c++) acc[a][b][c] = 0.f;

#pragma unroll
    for (int ks = 0; ks < 8; ks++) {
        int k0 = ks * 16;
        unsigned a[2][4], b[2][2];
#pragma unroll
        for (int sm_ = 0; sm_ < 2; sm_++) {
            const __half* ap = xh + (Rb + sm_ * 16 + gid) * XSTR + k0 + 2 * q;
            a[sm_][0] = *(const unsigned*)(ap);
            a[sm_][1] = *(const unsigned*)(ap + 8 * XSTR);
            a[sm_][2] = *(const unsigned*)(ap + 8);
            a[sm_][3] = *(const unsigned*)(ap + 8 * XSTR + 8);
        }
#pragma unroll
        for (int sn = 0; sn < 2; sn++) {
            const __half* bp = wt + (Cb + sn * 8 + gid) * XSTR + k0 + 2 * q;
            b[sn][0] = *(const unsigned*)(bp);
            b[sn][1] = *(const unsigned*)(bp + 8);
        }
#pragma unroll
        for (int sm_ = 0; sm_ < 2; sm_++)
#pragma unroll
            for (int sn = 0; sn < 2; sn++) {
                asm volatile(
                    "mma.sync.aligned.m16n8k16.row.col.f32.f16.f16.f32 "
                    "{%0,%1,%2,%3}, {%4,%5,%6,%7}, {%8,%9}, {%0,%1,%2,%3};\n"
                    : "+f"(acc[sm_][sn][0]), "+f"(acc[sm_][sn][1]),
                      "+f"(acc[sm_][sn][2]), "+f"(acc[sm_][sn][3])
                    : "r"(a[sm_][0]), "r"(a[sm_][1]), "r"(a[sm_][2]), "r"(a[sm_][3]),
                      "r"(b[sn][0]), "r"(b[sn][1]));
            }
    }

    // epilogue: dis-prescale + fp16 store
#pragma unroll
    for (int sm_ = 0; sm_ < 2; sm_++) {
        int r0 = row0 + Rb + sm_ * 16 + gid;
        int r1 = r0 + 8;
        float d0 = (r0 < n) ? g_dis[r0] : 0.f;
        float d1 = (r1 < n) ? g_dis[r1] : 0.f;
#pragma unroll
        for (int sn = 0; sn < 2; sn++) {
            int j2 = (Cb >> 1) + sn * 4 + q;   // half2 column index
            if (r0 < n)
                g_h0h[(size_t)r0 * 32 + j2] =
                    __floats2half2_rn(d0 * acc[sm_][sn][0], d0 * acc[sm_][sn][1]);
            if (r1 < n)
                g_h0h[(size_t)r1 * 32 + j2] =
                    __floats2half2_rn(d1 * acc[sm_][sn][2], d1 * acc[sm_][sn][3]);
        }
    }
}

// ====== GEMM 2 (proven FFMA config): gg = fp16(dis[row] * (h @ interleave(Wmu,Wls))) ======
__global__ void __launch_bounds__(256) gemm2_kernel(const float* __restrict__ Wmu,
                                                    const float* __restrict__ Wls, int n) {
    extern __shared__ float sm[];
    float* wsa = sm;
    float* wsb = sm + 2048;
    float* xs  = sm + 4096;
    int tid = threadIdx.x;
    for (int i = tid; i < 64 * 64; i += 256) {
        int k = i >> 6, j = i & 63;
        float v = (j < 32) ? Wmu[k * 32 + j] : Wls[k * 32 + (j - 32)];
        int jn = (j < 32) ? (2 * j) : (2 * (j - 32) + 1);
        int jt = jn >> 3, c = jn & 7;
        if (c < 4) wsa[k * 32 + jt * 4 + c] = v;
        else       wsb[k * 32 + jt * 4 + (c - 4)] = v;
    }
    int row0 = blockIdx.x * 128;
    int lane = tid & 31, wrp = tid >> 5;
    int rg4 = (wrp * 4 + (lane >> 3)) * 4;
    int jt  = lane & 7;
    float acc[4][8];
#pragma unroll
    for (int i = 0; i < 4; i++)
#pragma unroll
        for (int j = 0; j < 8; j++) acc[i][j] = 0.f;

    int frow = tid >> 3;
    int kq   = tid & 7;
    int csw  = ((kq & 3) << 3) | ((kq >> 2) << 2);

    for (int kc = 0; kc < 2; kc++) {
        __syncthreads();
#pragma unroll
        for (int it = 0; it < 4; it++) {
            int row  = frow + it * 32;
            int grow = row0 + row;
            float4 v = (grow < n) ? *(const float4*)(g_h + (size_t)grow * 64 + kc * 32 + kq * 4)
                                  : make_float4(0.f, 0.f, 0.f, 0.f);
            int rs = row ^ csw;
            xs[(kq * 4 + 0) * 132 + rs] = v.x;
            xs[(kq * 4 + 1) * 132 + rs] = v.y;
            xs[(kq * 4 + 2) * 132 + rs] = v.z;
            xs[(kq * 4 + 3) * 132 + rs] = v.w;
        }
        __syncthreads();
#pragma unroll
        for (int kk = 0; kk < 32; kk++) {
            int c = (((kk >> 2) & 3) << 3) | (((kk >> 4) & 1) << 2);
            float4 xv = *(const float4*)(xs + kk * 132 + (rg4 ^ c));
            int k = kc * 32 + kk;
            float4 a = *(const float4*)(wsa + k * 32 + jt * 4);
            float4 b = *(const float4*)(wsb + k * 32 + jt * 4);
            float xr[4] = {xv.x, xv.y, xv.z, xv.w};
#pragma unroll
            for (int i = 0; i < 4; i++) {
                acc[i][0] = fmaf(xr[i], a.x, acc[i][0]);
                acc[i][1] = fmaf(xr[i], a.y, acc[i][1]);
                acc[i][2] = fmaf(xr[i], a.z, acc[i][2]);
                acc[i][3] = fmaf(xr[i], a.w, acc[i][3]);
                acc[i][4] = fmaf(xr[i], b.x, acc[i][4]);
                acc[i][5] = fmaf(xr[i], b.y, acc[i][5]);
                acc[i][6] = fmaf(xr[i], b.z, acc[i][6]);
                acc[i][7] = fmaf(xr[i], b.w, acc[i][7]);
            }
        }
    }
#pragma unroll
    for (int i = 0; i < 4; i++) {
        int rr = row0 + rg4 + i;
        if (rr < n) {
            float di = g_dis[rr];
            __half2* o = g_ggh + (size_t)rr * 32 + jt * 4;
            o[0] = __floats2half2_rn(di*acc[i][0], di*acc[i][1]);
            o[1] = __floats2half2_rn(di*acc[i][2], di*acc[i][3]);
            o[2] = __floats2half2_rn(di*acc[i][4], di*acc[i][5]);
            o[3] = __floats2half2_rn(di*acc[i][6], di*acc[i][7]);
        }
    }
}

// -------- Conv1 (R12 config): half-warp/node, 4-edge unroll --------
__global__ void __launch_bounds__(256) conv1_kernel(const float* __restrict__ b1, int n) {
    int node = blockIdx.x * 16 + (threadIdx.x >> 4);
    int t    = threadIdx.x & 15;
    bool valid = node < n;
    int nd = valid ? node : 0;
    int st  = g_rowstart[nd];
    int cnt = valid ? g_indeg[nd] : 0;
    const int* cs = g_csr + st;
    const __half2* hb = g_h0h + 2 * t;
    float a0x=0.f,a0y=0.f,a0z=0.f,a0w=0.f, a1x=0.f,a1y=0.f,a1z=0.f,a1w=0.f;
    int e = 0;
    for (; e + 4 <= cnt; e += 4) {
        int s0 = cs[e], s1 = cs[e+1], s2 = cs[e+2], s3 = cs[e+3];
        uint2 u0 = *(const uint2*)(hb + (size_t)s0 * 32);
        uint2 u1 = *(const uint2*)(hb + (size_t)s1 * 32);
        uint2 u2 = *(const uint2*)(hb + (size_t)s2 * 32);
        uint2 u3 = *(const uint2*)(hb + (size_t)s3 * 32);
        float2 p0 = __half22float2(*(__half2*)&u0.x), q0 = __half22float2(*(__half2*)&u0.y);
        float2 p1 = __half22float2(*(__half2*)&u1.x), q1 = __half22float2(*(__half2*)&u1.y);
        float2 p2 = __half22float2(*(__half2*)&u2.x), q2 = __half22float2(*(__half2*)&u2.y);
        float2 p3 = __half22float2(*(__half2*)&u3.x), q3 = __half22float2(*(__half2*)&u3.y);
        a0x += p0.x; a0y += p0.y; a0z += q0.x; a0w += q0.y;
        a1x += p1.x; a1y += p1.y; a1z += q1.x; a1w += q1.y;
        a0x += p2.x; a0y += p2.y; a0z += q2.x; a0w += q2.y;
        a1x += p3.x; a1y += p3.y; a1z += q3.x; a1w += q3.y;
    }
    for (; e < cnt; e++) {
        uint2 u = *(const uint2*)(hb + (size_t)cs[e] * 32);
        float2 p = __half22float2(*(__half2*)&u.x), q = __half22float2(*(__half2*)&u.y);
        a0x += p.x; a0y += p.y; a0z += q.x; a0w += q.y;
    }
    uint2 us = *(const uint2*)(hb + (size_t)nd * 32);
    float2 ps = __half22float2(*(__half2*)&us.x), qs = __half22float2(*(__half2*)&us.y);
    float sx = a0x + a1x + ps.x;
    float sy = a0y + a1y + ps.y;
    float sz = a0z + a1z + qs.x;
    float sw = a0w + a1w + qs.y;
    float di = g_dis[nd];
    float4 bb = *(const float4*)(b1 + 4 * t);
    float vx = fmaxf(fmaf(di, sx, bb.x), 0.f);
    float vy = fmaxf(fmaf(di, sy, bb.y), 0.f);
    float vz = fmaxf(fmaf(di, sz, bb.z), 0.f);
    float vw = fmaxf(fmaf(di, sw, bb.w), 0.f);
    float ss = vx*vx + vy*vy + vz*vz + vw*vw;
#pragma unroll
    for (int o = 8; o > 0; o >>= 1) ss += __shfl_xor_sync(0xffffffffu, ss, o);
    float scale = 1.0f / fmaxf(sqrtf(ss), 1e-12f);
    if (valid)
        *(float4*)(g_h + (size_t)nd * 64 + 4 * t) =
            make_float4(vx*scale, vy*scale, vz*scale, vw*scale);
}

// -------- Conv2 + reparametrize (R12 config) --------
__global__ void __launch_bounds__(256) conv2_kernel(const float* __restrict__ bmu,
                                                    const float* __restrict__ bls,
                                                    const float* __restrict__ eps,
                                                    float* __restrict__ out_mu,
                                                    float* __restrict__ out_ls, int n) {
    int node = blockIdx.x * 16 + (threadIdx.x >> 4);
    int t    = threadIdx.x & 15;
    bool valid = node < n;
    int nd = valid ? node : 0;
    int st  = g_rowstart[nd];
    int cnt = valid ? g_indeg[nd] : 0;
    const int* cs = g_csr + st;
    const __half2* gb = g_ggh + 2 * t;
    float a0x=0.f,a0y=0.f,a0z=0.f,a0w=0.f, a1x=0.f,a1y=0.f,a1z=0.f,a1w=0.f;
    int e = 0;
    for (; e + 4 <= cnt; e += 4) {
        int s0 = cs[e], s1 = cs[e+1], s2 = cs[e+2], s3 = cs[e+3];
        uint2 u0 = *(const uint2*)(gb + (size_t)s0 * 32);
        uint2 u1 = *(const uint2*)(gb + (size_t)s1 * 32);
        uint2 u2 = *(const uint2*)(gb + (size_t)s2 * 32);
        uint2 u3 = *(const uint2*)(gb + (size_t)s3 * 32);
        float2 p0 = __half22float2(*(__half2*)&u0.x), q0 = __half22float2(*(__half2*)&u0.y);
        float2 p1 = __half22float2(*(__half2*)&u1.x), q1 = __half22float2(*(__half2*)&u1.y);
        float2 p2 = __half22float2(*(__half2*)&u2.x), q2 = __half22float2(*(__half2*)&u2.y);
        float2 p3 = __half22float2(*(__half2*)&u3.x), q3 = __half22float2(*(__half2*)&u3.y);
        a0x += p0.x; a0y += p0.y; a0z += q0.x; a0w += q0.y;
        a1x += p1.x; a1y += p1.y; a1z += q1.x; a1w += q1.y;
        a0x += p2.x; a0y += p2.y; a0z += q2.x; a0w += q2.y;
        a1x += p3.x; a1y += p3.y; a1z += q3.x; a1w += q3.y;
    }
    for (; e < cnt; e++) {
        uint2 u = *(const uint2*)(gb + (size_t)cs[e] * 32);
        float2 p = __half22float2(*(__half2*)&u.x), q = __half22float2(*(__half2*)&u.y);
        a0x += p.x; a0y += p.y; a0z += q.x; a0w += q.y;
    }
    if (!valid) return;
    uint2 us = *(const uint2*)(gb + (size_t)nd * 32);
    float2 ps = __half22float2(*(__half2*)&us.x), qs = __half22float2(*(__half2*)&us.y);
    float di = g_dis[nd];
    float mu0 = fmaf(di, a0x + a1x + ps.x, bmu[2*t]);
    float ls0 = fmaf(di, a0y + a1y + ps.y, bls[2*t]);
    float mu1 = fmaf(di, a0z + a1z + qs.x, bmu[2*t+1]);
    float ls1 = fmaf(di, a0w + a1w + qs.y, bls[2*t+1]);
    size_t oi = (size_t)nd * 32 + 2*t;
    *(float2*)(out_mu + oi) = make_float2(mu0, mu1);
    *(float2*)(out_ls + oi) = make_float2(ls0, ls1);
    float2 ep = *(const float2*)(eps + oi);
    float lc0 = fminf(fmaxf(ls0, -10.f), 10.f);
    float lc1 = fminf(fmaxf(ls1, -10.f), 10.f);
    float z0 = fmaf(ep.x, __expf(lc0), mu0);
    float z1 = fmaf(ep.y, __expf(lc1), mu1);
    *(__half2*)(g_zh + oi) = __floats2half2_rn(z0, z1);
}

// ---------------- decode: 4 lanes/edge, uint4 (16B) loads ----------------
__global__ void __launch_bounds__(256) decode_kernel(const int* __restrict__ src,
                                                     const int* __restrict__ dst,
                                                     float* __restrict__ out, int E) {
    int gid = blockIdx.x * 256 + threadIdx.x;
    int e   = gid >> 2;
    int sub = gid & 3;
    if (e >= E) return;
    int s = src[e], d = dst[e];
    uint4 ua = *(const uint4*)(g_zh + (size_t)s * 32 + sub * 8);
    uint4 ub = *(const uint4*)(g_zh + (size_t)d * 32 + sub * 8);
    float2 a0 = __half22float2(*reinterpret_cast<__half2*>(&ua.x));
    float2 a1 = __half22float2(*reinterpret_cast<__half2*>(&ua.y));
    float2 a2 = __half22float2(*reinterpret_cast<__half2*>(&ua.z));
    float2 a3 = __half22float2(*reinterpret_cast<__half2*>(&ua.w));
    float2 b0 = __half22float2(*reinterpret_cast<__half2*>(&ub.x));
    float2 b1 = __half22float2(*reinterpret_cast<__half2*>(&ub.y));
    float2 b2 = __half22float2(*reinterpret_cast<__half2*>(&ub.z));
    float2 b3 = __half22float2(*reinterpret_cast<__half2*>(&ub.w));
    float p = a0.x*b0.x + a0.y*b0.y + a1.x*b1.x + a1.y*b1.y
            + a2.x*b2.x + a2.y*b2.y + a3.x*b3.x + a3.y*b3.y;
    p += __shfl_xor_sync(0xffffffffu, p, 1);
    p += __shfl_xor_sync(0xffffffffu, p, 2);
    if (sub == 0) out[e] = 1.0f / (1.0f + __expf(-p));
}

// ---------------- launch (R12 schedule) ----------------
extern "C" void kernel_launch(void* const* d_in, const int* in_sizes, int n_in,
                              void* d_out, int out_size) {
    const float* x   = (const float*)d_in[0];
    const int*   ei  = (const int*)  d_in[1];
    const float* eps = (const float*)d_in[2];
    const float* W1  = (const float*)d_in[3];
    const float* b1  = (const float*)d_in[4];
    const float* Wmu = (const float*)d_in[5];
    const float* bmu = (const float*)d_in[6];
    const float* Wls = (const float*)d_in[7];
    const float* bls = (const float*)d_in[8];

    int n = in_sizes[0] / 128;
    int E = in_sizes[1] / 2;
    const int* src = ei;
    const int* dst = ei + E;

    float* out     = (float*)d_out;
    float* out_adj = out;
    float* out_mu  = out + E;
    float* out_ls  = out + E + (size_t)n * 32;

    const int SMEM2 = (2048 + 2048 + 32 * 132) * 4;   // 33280
    cudaFuncSetAttribute(gemm2_kernel, cudaFuncAttributeMaxDynamicSharedMemorySize, SMEM2);

    cudaStream_t s2;
    cudaEvent_t evFork, evJoin;
    cudaStreamCreateWithFlags(&s2, cudaStreamNonBlocking);
    cudaEventCreateWithFlags(&evFork, cudaEventDisableTiming);
    cudaEventCreateWithFlags(&evJoin, cudaEventDisableTiming);

    init_kernel<<<(n + 255) / 256, 256>>>(n);
    hist_kernel<<<(E + 255) / 256, 256>>>(dst, E);
    dis_kernel<<<(n + 255) / 256, 256>>>(n);

    // fork: gemm1 (TC) needs {x, W1, dis}; CSR build runs concurrently
    cudaEventRecord(evFork, 0);
    cudaStreamWaitEvent(s2, evFork, 0);
    gemm1_kernel<<<(n + 63) / 64, 256, 0, s2>>>(x, W1, n);
    cudaEventRecord(evJoin, s2);

    int nb = (n + 1023) / 1024;
    scan1_kernel<<<nb, 1024>>>(n);
    scan2_kernel<<<1, 256>>>(nb);
    scan3_kernel<<<(n + 255) / 256, 256>>>(n);
    fill_kernel<<<(E + 255) / 256, 256>>>(src, dst, E);

    cudaStreamWaitEvent(0, evJoin, 0);

    conv1_kernel<<<(n + 15) / 16, 256>>>(b1, n);
    gemm2_kernel<<<(n + 127) / 128, 256, SMEM2>>>(Wmu, Wls, n);
    conv2_kernel<<<(n + 15) / 16, 256>>>(bmu, bls, eps, out_mu, out_ls, n);
    decode_kernel<<<((size_t)E * 4 + 255) / 256, 256>>>(src, dst, out_adj, E);
}

// round 16
// speedup vs baseline: 1.0809x; 1.0412x over previous
#include <cuda_runtime.h>
#include <cuda_fp16.h>
#include <math.h>

#define MAXN 100000
#define MAXE 1600000

// ---------------- scratch ----------------
__device__ int     g_indeg[MAXN];
__device__ int     g_rowstart[MAXN];
__device__ int     g_cursor[MAXN];
__device__ int     g_bsum[256];
__device__ float   g_dis[MAXN];
__device__ int     g_csr[MAXE];
__device__ __half2 g_h0h[(size_t)MAXN * 32];    // fp16 dis-prescaled x@W1
__device__ float   g_h [(size_t)MAXN * 64];     // fp32 normalized hidden
__device__ __half2 g_ggh[(size_t)MAXN * 32];    // fp16 dis-prescaled (mu,ls) interleaved
__device__ __half  g_zh [(size_t)MAXN * 32];    // fp16 z

// ---------------- helpers ----------------
__device__ __forceinline__ void ldsm4(unsigned* r, const __half* p) {
    unsigned a = (unsigned)__cvta_generic_to_shared(p);
    asm volatile("ldmatrix.sync.aligned.m8n8.x4.shared.b16 {%0,%1,%2,%3}, [%4];"
                 : "=r"(r[0]), "=r"(r[1]), "=r"(r[2]), "=r"(r[3]) : "r"(a));
}
__device__ __forceinline__ void mma16816(float* c, const unsigned* a,
                                         unsigned b0, unsigned b1) {
    asm volatile(
        "mma.sync.aligned.m16n8k16.row.col.f32.f16.f16.f32 "
        "{%0,%1,%2,%3}, {%4,%5,%6,%7}, {%8,%9}, {%0,%1,%2,%3};\n"
        : "+f"(c[0]), "+f"(c[1]), "+f"(c[2]), "+f"(c[3])
        : "r"(a[0]), "r"(a[1]), "r"(a[2]), "r"(a[3]), "r"(b0), "r"(b1));
}

// ---------------- graph preprocessing ----------------
__global__ void init_kernel(int n) {
    int i = blockIdx.x * blockDim.x + threadIdx.x;
    if (i < n) g_indeg[i] = 0;
}

__global__ void hist_kernel(const int* __restrict__ dst, int E) {
    int e = blockIdx.x * blockDim.x + threadIdx.x;
    if (e < E) atomicAdd(&g_indeg[dst[e]], 1);
}

__global__ void dis_kernel(int n) {
    int i = blockIdx.x * blockDim.x + threadIdx.x;
    if (i < n) g_dis[i] = rsqrtf((float)(g_indeg[i] + 1));
}

__global__ void scan1_kernel(int n) {
    __shared__ int sm[1024];
    int t = threadIdx.x;
    int i = blockIdx.x * 1024 + t;
    int v = (i < n) ? g_indeg[i] : 0;
    sm[t] = v;
    __syncthreads();
#pragma unroll
    for (int o = 1; o < 1024; o <<= 1) {
        int tv = (t >= o) ? sm[t - o] : 0;
        __syncthreads();
        sm[t] += tv;
        __syncthreads();
    }
    if (i < n) g_rowstart[i] = sm[t] - v;
    if (t == 1023) g_bsum[blockIdx.x] = sm[1023];
}

__global__ void scan2_kernel(int nb) {
    __shared__ int sm[256];
    int t = threadIdx.x;
    int v = (t < nb) ? g_bsum[t] : 0;
    sm[t] = v;
    __syncthreads();
#pragma unroll
    for (int o = 1; o < 256; o <<= 1) {
        int tv = (t >= o) ? sm[t - o] : 0;
        __syncthreads();
        sm[t] += tv;
        __syncthreads();
    }
    if (t < nb) g_bsum[t] = sm[t] - v;
}

__global__ void scan3_kernel(int n) {
    int i = blockIdx.x * blockDim.x + threadIdx.x;
    if (i < n) {
        int v = g_rowstart[i] + g_bsum[i >> 10];
        g_rowstart[i] = v;
        g_cursor[i]   = v;
    }
}

__global__ void fill_kernel(const int* __restrict__ src, const int* __restrict__ dst, int E) {
    int e = blockIdx.x * blockDim.x + threadIdx.x;
    if (e < E) {
        int p = atomicAdd(&g_cursor[dst[e]], 1);
        g_csr[p] = src[e];
    }
}

// ============ GEMM 1 (TC + ldmatrix): h0h = fp16(dis[row] * (x @ W1)) ============
#define XSTR 136
__global__ void __launch_bounds__(256) gemm1_kernel(const float* __restrict__ x,
                                                    const float* __restrict__ W, int n) {
    __shared__ __half xh[64 * XSTR];
    __shared__ __half wt[64 * XSTR];
    int tid  = threadIdx.x;
    int row0 = blockIdx.x * 64;

    for (int i = tid; i < 64 * 64; i += 256) {
        int r = i >> 6, c2 = i & 63;
        int grow = row0 + r;
        float2 v = (grow < n) ? *(const float2*)(x + (size_t)grow * 128 + 2 * c2)
                              : make_float2(0.f, 0.f);
        *(__half2*)(xh + r * XSTR + 2 * c2) = __floats2half2_rn(v.x, v.y);
    }
    for (int i = tid; i < 128 * 16; i += 256) {
        int k = i >> 4, f4 = i & 15;
        float4 wv = *(const float4*)(W + k * 64 + f4 * 4);
        int j0 = f4 * 4;
        wt[(j0 + 0) * XSTR + k] = __float2half_rn(wv.x);
        wt[(j0 + 1) * XSTR + k] = __float2half_rn(wv.y);
        wt[(j0 + 2) * XSTR + k] = __float2half_rn(wv.z);
        wt[(j0 + 3) * XSTR + k] = __float2half_rn(wv.w);
    }
    __syncthreads();

    int w    = tid >> 5;
    int lane = tid & 31;
    int gid  = lane >> 2;
    int q    = lane & 3;
    int Rb   = (w & 1) * 32;
    int Cb   = (w >> 1) * 16;

    // ldmatrix per-lane addressing
    int arow = ((lane >> 3) & 1) * 8 + (lane & 7);   // row within 16-row A tile
    int akof = (lane >> 4) * 8;                      // k-half for A
    int bj   = (lane >> 4) * 8 + (lane & 7);         // col within 16-col B tile
    int bkof = ((lane >> 3) & 1) * 8;                // k-half for B

    float acc[2][2][4];
#pragma unroll
    for (int a = 0; a < 2; a++)
#pragma unroll
        for (int b = 0; b < 2; b++)
#pragma unroll
            for (int c = 0; c < 4; c++) acc[a][b][c] = 0.f;

#pragma unroll
    for (int ks = 0; ks < 8; ks++) {
        int k0 = ks * 16;
        unsigned A0[4], A1[4], B[4];
        ldsm4(A0, xh + (Rb + arow) * XSTR + k0 + akof);
        ldsm4(A1, xh + (Rb + 16 + arow) * XSTR + k0 + akof);
        ldsm4(B,  wt + (Cb + bj) * XSTR + k0 + bkof);
        mma16816(acc[0][0], A0, B[0], B[1]);
        mma16816(acc[0][1], A0, B[2], B[3]);
        mma16816(acc[1][0], A1, B[0], B[1]);
        mma16816(acc[1][1], A1, B[2], B[3]);
    }

#pragma unroll
    for (int sm_ = 0; sm_ < 2; sm_++) {
        int r0 = row0 + Rb + sm_ * 16 + gid;
        int r1 = r0 + 8;
        float d0 = (r0 < n) ? g_dis[r0] : 0.f;
        float d1 = (r1 < n) ? g_dis[r1] : 0.f;
#pragma unroll
        for (int sn = 0; sn < 2; sn++) {
            int j2 = (Cb >> 1) + sn * 4 + q;
            if (r0 < n)
                g_h0h[(size_t)r0 * 32 + j2] =
                    __floats2half2_rn(d0 * acc[sm_][sn][0], d0 * acc[sm_][sn][1]);
            if (r1 < n)
                g_h0h[(size_t)r1 * 32 + j2] =
                    __floats2half2_rn(d1 * acc[sm_][sn][2], d1 * acc[sm_][sn][3]);
        }
    }
}

// ====== GEMM 2 (TC + ldmatrix): gg = fp16(dis[row] * (h @ interleave(Wmu,Wls))) ======
#define XSTR2 72
__global__ void __launch_bounds__(256) gemm2_kernel(const float* __restrict__ Wmu,
                                                    const float* __restrict__ Wls, int n) {
    __shared__ __half xh[64 * XSTR2];
    __shared__ __half wt[64 * XSTR2];
    int tid  = threadIdx.x;
    int row0 = blockIdx.x * 64;

    // stage h [64][64] fp32 -> fp16
    for (int i = tid; i < 64 * 32; i += 256) {
        int r = i >> 5, c2 = i & 31;
        int grow = row0 + r;
        float2 v = (grow < n) ? *(const float2*)(g_h + (size_t)grow * 64 + 2 * c2)
                              : make_float2(0.f, 0.f);
        *(__half2*)(xh + r * XSTR2 + 2 * c2) = __floats2half2_rn(v.x, v.y);
    }
    // stage interleaved W^T: wt[jn][k], jn even=mu col, odd=ls col
    for (int i = tid; i < 64 * 64; i += 256) {
        int k = i >> 6, j = i & 63;
        float v = (j < 32) ? Wmu[k * 32 + j] : Wls[k * 32 + (j - 32)];
        int jn = (j < 32) ? (2 * j) : (2 * (j - 32) + 1);
        wt[jn * XSTR2 + k] = __float2half_rn(v);
    }
    __syncthreads();

    int w    = tid >> 5;
    int lane = tid & 31;
    int gid  = lane >> 2;
    int q    = lane & 3;
    int Rb   = (w & 1) * 32;
    int Cb   = (w >> 1) * 16;

    int arow = ((lane >> 3) & 1) * 8 + (lane & 7);
    int akof = (lane >> 4) * 8;
    int bj   = (lane >> 4) * 8 + (lane & 7);
    int bkof = ((lane >> 3) & 1) * 8;

    float acc[2][2][4];
#pragma unroll
    for (int a = 0; a < 2; a++)
#pragma unroll
        for (int b = 0; b < 2; b++)
#pragma unroll
            for (int c = 0; c < 4; c++) acc[a][b][c] = 0.f;

#pragma unroll
    for (int ks = 0; ks < 4; ks++) {
        int k0 = ks * 16;
        unsigned A0[4], A1[4], B[4];
        ldsm4(A0, xh + (Rb + arow) * XSTR2 + k0 + akof);
        ldsm4(A1, xh + (Rb + 16 + arow) * XSTR2 + k0 + akof);
        ldsm4(B,  wt + (Cb + bj) * XSTR2 + k0 + bkof);
        mma16816(acc[0][0], A0, B[0], B[1]);
        mma16816(acc[0][1], A0, B[2], B[3]);
        mma16816(acc[1][0], A1, B[0], B[1]);
        mma16816(acc[1][1], A1, B[2], B[3]);
    }

#pragma unroll
    for (int sm_ = 0; sm_ < 2; sm_++) {
        int r0 = row0 + Rb + sm_ * 16 + gid;
        int r1 = r0 + 8;
        float d0 = (r0 < n) ? g_dis[r0] : 0.f;
        float d1 = (r1 < n) ? g_dis[r1] : 0.f;
#pragma unroll
        for (int sn = 0; sn < 2; sn++) {
            int j2 = (Cb >> 1) + sn * 4 + q;
            if (r0 < n)
                g_ggh[(size_t)r0 * 32 + j2] =
                    __floats2half2_rn(d0 * acc[sm_][sn][0], d0 * acc[sm_][sn][1]);
            if (r1 < n)
                g_ggh[(size_t)r1 * 32 + j2] =
                    __floats2half2_rn(d1 * acc[sm_][sn][2], d1 * acc[sm_][sn][3]);
        }
    }
}

// -------- Conv1 (R12 config): half-warp/node, 4-edge unroll --------
__global__ void __launch_bounds__(256) conv1_kernel(const float* __restrict__ b1, int n) {
    int node = blockIdx.x * 16 + (threadIdx.x >> 4);
    int t    = threadIdx.x & 15;
    bool valid = node < n;
    int nd = valid ? node : 0;
    int st  = g_rowstart[nd];
    int cnt = valid ? g_indeg[nd] : 0;
    const int* cs = g_csr + st;
    const __half2* hb = g_h0h + 2 * t;
    float a0x=0.f,a0y=0.f,a0z=0.f,a0w=0.f, a1x=0.f,a1y=0.f,a1z=0.f,a1w=0.f;
    int e = 0;
    for (; e + 4 <= cnt; e += 4) {
        int s0 = cs[e], s1 = cs[e+1], s2 = cs[e+2], s3 = cs[e+3];
        uint2 u0 = *(const uint2*)(hb + (size_t)s0 * 32);
        uint2 u1 = *(const uint2*)(hb + (size_t)s1 * 32);
        uint2 u2 = *(const uint2*)(hb + (size_t)s2 * 32);
        uint2 u3 = *(const uint2*)(hb + (size_t)s3 * 32);
        float2 p0 = __half22float2(*(__half2*)&u0.x), q0 = __half22float2(*(__half2*)&u0.y);
        float2 p1 = __half22float2(*(__half2*)&u1.x), q1 = __half22float2(*(__half2*)&u1.y);
        float2 p2 = __half22float2(*(__half2*)&u2.x), q2 = __half22float2(*(__half2*)&u2.y);
        float2 p3 = __half22float2(*(__half2*)&u3.x), q3 = __half22float2(*(__half2*)&u3.y);
        a0x += p0.x; a0y += p0.y; a0z += q0.x; a0w += q0.y;
        a1x += p1.x; a1y += p1.y; a1z += q1.x; a1w += q1.y;
        a0x += p2.x; a0y += p2.y; a0z += q2.x; a0w += q2.y;
        a1x += p3.x; a1y += p3.y; a1z += q3.x; a1w += q3.y;
    }
    for (; e < cnt; e++) {
        uint2 u = *(const uint2*)(hb + (size_t)cs[e] * 32);
        float2 p = __half22float2(*(__half2*)&u.x), q = __half22float2(*(__half2*)&u.y);
        a0x += p.x; a0y += p.y; a0z += q.x; a0w += q.y;
    }
    uint2 us = *(const uint2*)(hb + (size_t)nd * 32);
    float2 ps = __half22float2(*(__half2*)&us.x), qs = __half22float2(*(__half2*)&us.y);
    float sx = a0x + a1x + ps.x;
    float sy = a0y + a1y + ps.y;
    float sz = a0z + a1z + qs.x;
    float sw = a0w + a1w + qs.y;
    float di = g_dis[nd];
    float4 bb = *(const float4*)(b1 + 4 * t);
    float vx = fmaxf(fmaf(di, sx, bb.x), 0.f);
    float vy = fmaxf(fmaf(di, sy, bb.y), 0.f);
    float vz = fmaxf(fmaf(di, sz, bb.z), 0.f);
    float vw = fmaxf(fmaf(di, sw, bb.w), 0.f);
    float ss = vx*vx + vy*vy + vz*vz + vw*vw;
#pragma unroll
    for (int o = 8; o > 0; o >>= 1) ss += __shfl_xor_sync(0xffffffffu, ss, o);
    float scale = 1.0f / fmaxf(sqrtf(ss), 1e-12f);
    if (valid)
        *(float4*)(g_h + (size_t)nd * 64 + 4 * t) =
            make_float4(vx*scale, vy*scale, vz*scale, vw*scale);
}

// -------- Conv2 + reparametrize (R12 config) --------
__global__ void __launch_bounds__(256) conv2_kernel(const float* __restrict__ bmu,
                                                    const float* __restrict__ bls,
                                                    const float* __restrict__ eps,
                                                    float* __restrict__ out_mu,
                                                    float* __restrict__ out_ls, int n) {
    int node = blockIdx.x * 16 + (threadIdx.x >> 4);
    int t    = threadIdx.x & 15;
    bool valid = node < n;
    int nd = valid ? node : 0;
    int st  = g_rowstart[nd];
    int cnt = valid ? g_indeg[nd] : 0;
    const int* cs = g_csr + st;
    const __half2* gb = g_ggh + 2 * t;
    float a0x=0.f,a0y=0.f,a0z=0.f,a0w=0.f, a1x=0.f,a1y=0.f,a1z=0.f,a1w=0.f;
    int e = 0;
    for (; e + 4 <= cnt; e += 4) {
        int s0 = cs[e], s1 = cs[e+1], s2 = cs[e+2], s3 = cs[e+3];
        uint2 u0 = *(const uint2*)(gb + (size_t)s0 * 32);
        uint2 u1 = *(const uint2*)(gb + (size_t)s1 * 32);
        uint2 u2 = *(const uint2*)(gb + (size_t)s2 * 32);
        uint2 u3 = *(const uint2*)(gb + (size_t)s3 * 32);
        float2 p0 = __half22float2(*(__half2*)&u0.x), q0 = __half22float2(*(__half2*)&u0.y);
        float2 p1 = __half22float2(*(__half2*)&u1.x), q1 = __half22float2(*(__half2*)&u1.y);
        float2 p2 = __half22float2(*(__half2*)&u2.x), q2 = __half22float2(*(__half2*)&u2.y);
        float2 p3 = __half22float2(*(__half2*)&u3.x), q3 = __half22float2(*(__half2*)&u3.y);
        a0x += p0.x; a0y += p0.y; a0z += q0.x; a0w += q0.y;
        a1x += p1.x; a1y += p1.y; a1z += q1.x; a1w += q1.y;
        a0x += p2.x; a0y += p2.y; a0z += q2.x; a0w += q2.y;
        a1x += p3.x; a1y += p3.y; a1z += q3.x; a1w += q3.y;
    }
    for (; e < cnt; e++) {
        uint2 u = *(const uint2*)(gb + (size_t)cs[e] * 32);
        float2 p = __half22float2(*(__half2*)&u.x), q = __half22float2(*(__half2*)&u.y);
        a0x += p.x; a0y += p.y; a0z += q.x; a0w += q.y;
    }
    if (!valid) return;
    uint2 us = *(const uint2*)(gb + (size_t)nd * 32);
    float2 ps = __half22float2(*(__half2*)&us.x), qs = __half22float2(*(__half2*)&us.y);
    float di = g_dis[nd];
    float mu0 = fmaf(di, a0x + a1x + ps.x, bmu[2*t]);
    float ls0 = fmaf(di, a0y + a1y + ps.y, bls[2*t]);
    float mu1 = fmaf(di, a0z + a1z + qs.x, bmu[2*t+1]);
    float ls1 = fmaf(di, a0w + a1w + qs.y, bls[2*t+1]);
    size_t oi = (size_t)nd * 32 + 2*t;
    *(float2*)(out_mu + oi) = make_float2(mu0, mu1);
    *(float2*)(out_ls + oi) = make_float2(ls0, ls1);
    float2 ep = *(const float2*)(eps + oi);
    float lc0 = fminf(fmaxf(ls0, -10.f), 10.f);
    float lc1 = fminf(fmaxf(ls1, -10.f), 10.f);
    float z0 = fmaf(ep.x, __expf(lc0), mu0);
    float z1 = fmaf(ep.y, __expf(lc1), mu1);
    *(__half2*)(g_zh + oi) = __floats2half2_rn(z0, z1);
}

// ---------------- decode: 4 lanes/edge, uint4 (16B) loads ----------------
__global__ void __launch_bounds__(256) decode_kernel(const int* __restrict__ src,
                                                     const int* __restrict__ dst,
                                                     float* __restrict__ out, int E) {
    int gid = blockIdx.x * 256 + threadIdx.x;
    int e   = gid >> 2;
    int sub = gid & 3;
    if (e >= E) return;
    int s = src[e], d = dst[e];
    uint4 ua = *(const uint4*)(g_zh + (size_t)s * 32 + sub * 8);
    uint4 ub = *(const uint4*)(g_zh + (size_t)d * 32 + sub * 8);
    float2 a0 = __half22float2(*reinterpret_cast<__half2*>(&ua.x));
    float2 a1 = __half22float2(*reinterpret_cast<__half2*>(&ua.y));
    float2 a2 = __half22float2(*reinterpret_cast<__half2*>(&ua.z));
    float2 a3 = __half22float2(*reinterpret_cast<__half2*>(&ua.w));
    float2 b0 = __half22float2(*reinterpret_cast<__half2*>(&ub.x));
    float2 b1 = __half22float2(*reinterpret_cast<__half2*>(&ub.y));
    float2 b2 = __half22float2(*reinterpret_cast<__half2*>(&ub.z));
    float2 b3 = __half22float2(*reinterpret_cast<__half2*>(&ub.w));
    float p = a0.x*b0.x + a0.y*b0.y + a1.x*b1.x + a1.y*b1.y
            + a2.x*b2.x + a2.y*b2.y + a3.x*b3.x + a3.y*b3.y;
    p += __shfl_xor_sync(0xffffffffu, p, 1);
    p += __shfl_xor_sync(0xffffffffu, p, 2);
    if (sub == 0) out[e] = 1.0f / (1.0f + __expf(-p));
}

// ---------------- launch (R12 schedule) ----------------
extern "C" void kernel_launch(void* const* d_in, const int* in_sizes, int n_in,
                              void* d_out, int out_size) {
    const float* x   = (const float*)d_in[0];
    const int*   ei  = (const int*)  d_in[1];
    const float* eps = (const float*)d_in[2];
    const float* W1  = (const float*)d_in[3];
    const float* b1  = (const float*)d_in[4];
    const float* Wmu = (const float*)d_in[5];
    const float* bmu = (const float*)d_in[6];
    const float* Wls = (const float*)d_in[7];
    const float* bls = (const float*)d_in[8];

    int n = in_sizes[0] / 128;
    int E = in_sizes[1] / 2;
    const int* src = ei;
    const int* dst = ei + E;

    float* out     = (float*)d_out;
    float* out_adj = out;
    float* out_mu  = out + E;
    float* out_ls  = out + E + (size_t)n * 32;

    cudaStream_t s2;
    cudaEvent_t evFork, evJoin;
    cudaStreamCreateWithFlags(&s2, cudaStreamNonBlocking);
    cudaEventCreateWithFlags(&evFork, cudaEventDisableTiming);
    cudaEventCreateWithFlags(&evJoin, cudaEventDisableTiming);

    init_kernel<<<(n + 255) / 256, 256>>>(n);
    hist_kernel<<<(E + 255) / 256, 256>>>(dst, E);
    dis_kernel<<<(n + 255) / 256, 256>>>(n);

    // fork: gemm1 (TC) needs {x, W1, dis}; CSR build runs concurrently
    cudaEventRecord(evFork, 0);
    cudaStreamWaitEvent(s2, evFork, 0);
    gemm1_kernel<<<(n + 63) / 64, 256, 0, s2>>>(x, W1, n);
    cudaEventRecord(evJoin, s2);

    int nb = (n + 1023) / 1024;
    scan1_kernel<<<nb, 1024>>>(n);
    scan2_kernel<<<1, 256>>>(nb);
    scan3_kernel<<<(n + 255) / 256, 256>>>(n);
    fill_kernel<<<(E + 255) / 256, 256>>>(src, dst, E);

    cudaStreamWaitEvent(0, evJoin, 0);

    conv1_kernel<<<(n + 15) / 16, 256>>>(b1, n);
    gemm2_kernel<<<(n + 63) / 64, 256>>>(Wmu, Wls, n);
    conv2_kernel<<<(n + 15) / 16, 256>>>(bmu, bls, eps, out_mu, out_ls, n);
    decode_kernel<<<((size_t)E * 4 + 255) / 256, 256>>>(src, dst, out_adj, E);
}